// round 12
// baseline (speedup 1.0000x reference)
#include <cuda_runtime.h>

// Problem constants (fixed by the reference):
//   B=4, C=32, H=64, W=64, K=64, pool block 2x2
#define KK     64
#define HW     4096
#define MAXN   1024      // k-major capacity per RF (actual support <= ~950)
#define NBC    128       // B*C
#define NTH    256
#define PADW   4100      // padded u-tile stride (floats): 16B-aligned, bank shift 4

// Static device scratch (no allocation allowed).
// k-major list: bits[31:20]=pixel idx, bits[19:0]=rf quantized to 20 bits.
__device__ unsigned int g_list[KK * MAXN];        // 256 KB
__device__ int          g_cnt[KK];
// pixel-major list: slot j of pixel x at [j*HW + x] (coalesced over x).
// bits[31:26]=k, bits[25:0]=rf quantized to 26 bits.
__device__ unsigned int g_plist[KK * HW];         // 1 MB
__device__ int          g_pcnt[HW];
// per-(bc,k) inverse denominators
__device__ float        g_inv[NBC * KK];          // 32 KB

#define QS20     1048575.0f
#define INV_Q20  (1.0f / 1048575.0f)
#define QS26     67108863.0f
#define INV_Q26  (1.0f / 67108863.0f)

// ---------------------------------------------------------------------------
// Build (merged, 128 CTAs):
//   blocks [0,64):   k-major list compaction (shuffle scan, 2 barriers).
//   blocks [64,128): pixel-major lists, 64 pixels/CTA, FOUR threads per pixel
//                    (16 k's each, preloaded into registers => MLP 16, one
//                    latency trip; quarters stitched via smem prefix).
// Fixed orders => bit-identical lists every call.
// ---------------------------------------------------------------------------
__global__ __launch_bounds__(NTH) void build_all(const float* __restrict__ rfs) {
    const int tid  = threadIdx.x;
    const int lane = tid & 31;
    const int wid  = tid >> 5;

    if (blockIdx.x < KK) {
        // ---- k-major compaction for k = blockIdx.x ----
        const int k = blockIdx.x;
        const float* __restrict__ r = rfs + k * HW;

        __shared__ int wsum[NTH / 32];
        __shared__ int woff[NTH / 32];

        float vals[16];
        const int base = tid * 16;
#pragma unroll
        for (int i = 0; i < 16; i += 4) {
            float4 v = *reinterpret_cast<const float4*>(r + base + i);
            vals[i] = v.x; vals[i + 1] = v.y; vals[i + 2] = v.z; vals[i + 3] = v.w;
        }
        int c = 0;
#pragma unroll
        for (int i = 0; i < 16; i++) c += (vals[i] > 0.0f);

        int inc = c;  // warp inclusive scan
#pragma unroll
        for (int off = 1; off < 32; off <<= 1) {
            int t = __shfl_up_sync(0xffffffffu, inc, off);
            if (lane >= off) inc += t;
        }
        if (lane == 31) wsum[wid] = inc;
        __syncthreads();
        if (wid == 0) {
            int v = (lane < NTH / 32) ? wsum[lane] : 0;
#pragma unroll
            for (int off = 1; off < NTH / 32; off <<= 1) {
                int t = __shfl_up_sync(0xffffffffu, v, off);
                if (lane >= off) v += t;
            }
            if (lane < NTH / 32) woff[lane] = v - wsum[lane];
            if (lane == NTH / 32 - 1) g_cnt[k] = v;
        }
        __syncthreads();

        int pos = woff[wid] + (inc - c);
        const int ob = k * MAXN;
#pragma unroll
        for (int i = 0; i < 16; i++) {
            if (vals[i] > 0.0f) {
                unsigned int q = (unsigned int)(vals[i] * QS20 + 0.5f);
                if (pos < MAXN)
                    g_list[ob + pos] = ((unsigned int)(base + i) << 20) | q;
                pos++;
            }
        }
    } else {
        // ---- pixel-major lists: 64 pixels/CTA, 4 threads/pixel ----
        __shared__ int cq[4][64];

        const int pl = tid & 63;                       // local pixel
        const int qh = tid >> 6;                       // k-quarter: 0..3
        const int p  = (blockIdx.x - KK) * 64 + pl;    // global pixel
        const int kb = qh * 16;                        // k base for this quarter

        float vals[16];
#pragma unroll
        for (int i = 0; i < 16; i++)                   // 16 independent loads
            vals[i] = rfs[(kb + i) * HW + p];

        int c = 0;
#pragma unroll
        for (int i = 0; i < 16; i++) c += (vals[i] > 0.0f);

        cq[qh][pl] = c;
        __syncthreads();

        int n = 0;
#pragma unroll
        for (int h = 0; h < 4; h++) n += (h < qh) ? cq[h][pl] : 0;  // start
#pragma unroll
        for (int i = 0; i < 16; i++) {
            if (vals[i] > 0.0f) {
                g_plist[n * HW + p] = ((unsigned int)(kb + i) << 26) |
                                      (unsigned int)(vals[i] * QS26 + 0.5f);
                n++;
            }
        }
        if (qh == 3) g_pcnt[p] = n;                    // total count
    }
}

// ---------------------------------------------------------------------------
// Denominators, bc-batched x4: grid = (NBC/4)*8 = 256 CTAs.
// CTA = (bc-group, octet of 8 k's). 4 padded u tiles in dynamic smem; each
// warp owns ONE k, loads each list entry once, computes 4 exp (one per bc),
// warp-shuffle reduces 4 accumulators. No mainloop barriers.
// Numerics: e/denom == exp(v-m)/(exp(-m)+Sum exp(v-m)) exactly; |v| small.
// ---------------------------------------------------------------------------
__global__ __launch_bounds__(NTH) void denom_kernel(const float* __restrict__ u) {
    extern __shared__ float u_s[];   // 4 * PADW floats

    const int bcg  = blockIdx.x >> 3;
    const int oct  = blockIdx.x & 7;
    const int bc0  = bcg * 4;
    const int tid  = threadIdx.x;
    const int lane = tid & 31;
    const int wid  = tid >> 5;

    // load 4 u tiles (coalesced float4), padded stride => per-bc bank shift 4
#pragma unroll
    for (int b = 0; b < 4; b++) {
        const float4* __restrict__ src =
            reinterpret_cast<const float4*>(u + (bc0 + b) * HW);
        float4* dst = reinterpret_cast<float4*>(u_s + b * PADW);
#pragma unroll
        for (int i = 0; i < HW / 4 / NTH; i++)
            dst[tid + i * NTH] = src[tid + i * NTH];
    }
    __syncthreads();

    const int k   = oct * 8 + wid;
    int cnt = g_cnt[k];
    cnt = (cnt > MAXN) ? MAXN : cnt;   // OOB guard only; never taken
    const unsigned int* __restrict__ ls = g_list + k * MAXN;

    float s0 = 0.f, s1 = 0.f, s2 = 0.f, s3 = 0.f;
    const int trips = (cnt + 31) >> 5;
#pragma unroll 4
    for (int j = 0; j < trips; j++) {
        const int t = lane + j * 32;
        const unsigned int e = ls[t];              // in-bounds (capacity MAXN)
        const int   idx = (int)(e >> 20);
        const float rf  = (float)(e & 0xFFFFFu) * INV_Q20;
        const bool  p   = (t < cnt);
        const float e0 = __expf(u_s[idx] * rf);
        const float e1 = __expf(u_s[idx + PADW] * rf);
        const float e2 = __expf(u_s[idx + 2 * PADW] * rf);
        const float e3 = __expf(u_s[idx + 3 * PADW] * rf);
        s0 += p ? e0 : 0.f;  s1 += p ? e1 : 0.f;
        s2 += p ? e2 : 0.f;  s3 += p ? e3 : 0.f;
    }
#pragma unroll
    for (int o = 16; o; o >>= 1) {
        s0 += __shfl_xor_sync(0xffffffffu, s0, o);
        s1 += __shfl_xor_sync(0xffffffffu, s1, o);
        s2 += __shfl_xor_sync(0xffffffffu, s2, o);
        s3 += __shfl_xor_sync(0xffffffffu, s3, o);
    }
    if (lane == 0) {
        g_inv[(bc0 + 0) * KK + k] = __fdividef(1.f, 1.f + s0);
        g_inv[(bc0 + 1) * KK + k] = __fdividef(1.f, 1.f + s1);
        g_inv[(bc0 + 2) * KK + k] = __fdividef(1.f, 1.f + s2);
        g_inv[(bc0 + 3) * KK + k] = __fdividef(1.f, 1.f + s3);
    }
}

// ---------------------------------------------------------------------------
// Gather + pool, bc-batched x4: grid = (NBC/4)*8 = 256 CTAs, 128 threads.
// Each thread owns one 2x2 output block for 4 bc's: 16 register accumulators;
// each j-iteration loads 2 uint2 (4 entries) and feeds 16 exp+FMA chains.
// Fixed per-pixel order => deterministic.
// ---------------------------------------------------------------------------
__global__ __launch_bounds__(128) void gather_kernel(const float* __restrict__ u,
                                                     float* __restrict__ out) {
    __shared__ float inv_s[4 * KK];

    const int bcg = blockIdx.x >> 3;
    const int rg  = blockIdx.x & 7;
    const int bc0 = bcg * 4;
    const int tid = threadIdx.x;

    inv_s[tid]       = g_inv[bc0 * KK + tid];
    inv_s[tid + 128] = g_inv[bc0 * KK + tid + 128];
    __syncthreads();

    const int o   = rg * 128 + tid;       // output index in [0,1024)
    const int oy  = o >> 5;
    const int ox  = o & 31;
    const int p00 = oy * 128 + ox * 2;    // top-left pixel of the 2x2 block

    // u values: up[b][i], 4 bc x 4 pixels
    float up[4][4];
#pragma unroll
    for (int b = 0; b < 4; b++) {
        const float* __restrict__ ub = u + (bc0 + b) * HW;
        const float2 ua = *reinterpret_cast<const float2*>(ub + p00);
        const float2 uc = *reinterpret_cast<const float2*>(ub + p00 + 64);
        up[b][0] = ua.x; up[b][1] = ua.y; up[b][2] = uc.x; up[b][3] = uc.y;
    }

    int n[4];
    {
        const int2 na = *reinterpret_cast<const int2*>(g_pcnt + p00);
        const int2 nb = *reinterpret_cast<const int2*>(g_pcnt + p00 + 64);
        n[0] = na.x; n[1] = na.y; n[2] = nb.x; n[3] = nb.y;
    }
    int mx = n[0];
#pragma unroll
    for (int i = 1; i < 4; i++) mx = (n[i] > mx) ? n[i] : mx;

    float acc[4][4] = {};
#pragma unroll 2
    for (int j = 0; j < mx; j++) {
        const unsigned int* __restrict__ row = g_plist + j * HW + p00;
        const uint2 ea = *reinterpret_cast<const uint2*>(row);        // px0,px1
        const uint2 eb = *reinterpret_cast<const uint2*>(row + 64);   // px2,px3
        const unsigned int ent[4] = {ea.x, ea.y, eb.x, eb.y};
#pragma unroll
        for (int i = 0; i < 4; i++) {
            const float rf = (float)(ent[i] & 0x3FFFFFFu) * INV_Q26;
            const int   kk = (int)(ent[i] >> 26);
            const bool  p  = (j < n[i]);
#pragma unroll
            for (int b = 0; b < 4; b++) {
                const float e = __expf(up[b][i] * rf) * inv_s[b * KK + kk];
                acc[b][i] += p ? e : 0.f;
            }
        }
    }

#pragma unroll
    for (int b = 0; b < 4; b++)
        out[(bc0 + b) * 1024 + o] = fmaxf(fmaxf(acc[b][0], acc[b][1]),
                                          fmaxf(acc[b][2], acc[b][3]));
}

extern "C" void kernel_launch(void* const* d_in, const int* in_sizes, int n_in,
                              void* d_out, int out_size) {
    const float* u   = (const float*)d_in[0];  // (B,C,H,W) = 524288 f32
    const float* rfs = (const float*)d_in[1];  // (K,H,W)   = 262144 f32
    float* out = (float*)d_out;                // (B,C,32,32) = 131072 f32

    const int dsm = 4 * PADW * (int)sizeof(float);  // 65600 B
    cudaFuncSetAttribute(denom_kernel,
                         cudaFuncAttributeMaxDynamicSharedMemorySize, dsm);

    build_all<<<KK + HW / 64, NTH>>>(rfs);          // 128 CTAs
    denom_kernel<<<(NBC / 4) * 8, NTH, dsm>>>(u);   // 256 CTAs
    gather_kernel<<<(NBC / 4) * 8, 128>>>(u, out);  // 256 CTAs
}

// round 14
// speedup vs baseline: 1.0707x; 1.0707x over previous
#include <cuda_runtime.h>

// Problem constants (fixed by the reference):
//   B=4, C=32, H=64, W=64, K=64, pool block 2x2
#define KK     64
#define HW     4096
#define NBLK   1024      // number of 2x2 output blocks per image
#define MAXN   1024      // k-major capacity per RF (actual support <= ~950)
#define NBC    128       // B*C
#define NTH    256

// Static device scratch (no allocation allowed).
// k-major list: bits[31:20]=pixel idx, bits[19:0]=rf quantized to 20 bits.
__device__ unsigned int g_list[KK * MAXN];        // 256 KB
__device__ int          g_cnt[KK];
// blocked pixel-major list: entries for the 4 pixels of 2x2 block o at slot j
// live in one uint4 at [j*4096 + o*4 + sub]. bits[31:26]=k, [25:0]=rf q26.
__device__ unsigned int g_p4[KK * HW];            // 1 MB
__device__ int          g_n4[HW];                 // per-(block,sub) counts, int4-loadable
// per-(bc,k) inverse denominators
__device__ float        g_inv[NBC * KK];          // 32 KB

#define QS20     1048575.0f
#define INV_Q20  (1.0f / 1048575.0f)
#define QS26     67108863.0f
#define INV_Q26  (1.0f / 67108863.0f)

// ---------------------------------------------------------------------------
// Build (merged, 128 CTAs):
//   blocks [0,64):   k-major list compaction (shuffle scan, 2 barriers).
//   blocks [64,128): blocked pixel-major lists, 64 pixels/CTA, 4 threads per
//                    pixel (16 k's each preloaded => MLP 16, one latency trip;
//                    quarters stitched via smem prefix). k-ascending order.
// Fixed orders => bit-identical lists every call.
// ---------------------------------------------------------------------------
__global__ __launch_bounds__(NTH) void build_all(const float* __restrict__ rfs) {
    const int tid  = threadIdx.x;
    const int lane = tid & 31;
    const int wid  = tid >> 5;

    if (blockIdx.x < KK) {
        // ---- k-major compaction for k = blockIdx.x ----
        const int k = blockIdx.x;
        const float* __restrict__ r = rfs + k * HW;

        __shared__ int wsum[NTH / 32];
        __shared__ int woff[NTH / 32];

        float vals[16];
        const int base = tid * 16;
#pragma unroll
        for (int i = 0; i < 16; i += 4) {
            float4 v = *reinterpret_cast<const float4*>(r + base + i);
            vals[i] = v.x; vals[i + 1] = v.y; vals[i + 2] = v.z; vals[i + 3] = v.w;
        }
        int c = 0;
#pragma unroll
        for (int i = 0; i < 16; i++) c += (vals[i] > 0.0f);

        int inc = c;  // warp inclusive scan
#pragma unroll
        for (int off = 1; off < 32; off <<= 1) {
            int t = __shfl_up_sync(0xffffffffu, inc, off);
            if (lane >= off) inc += t;
        }
        if (lane == 31) wsum[wid] = inc;
        __syncthreads();
        if (wid == 0) {
            int v = (lane < NTH / 32) ? wsum[lane] : 0;
#pragma unroll
            for (int off = 1; off < NTH / 32; off <<= 1) {
                int t = __shfl_up_sync(0xffffffffu, v, off);
                if (lane >= off) v += t;
            }
            if (lane < NTH / 32) woff[lane] = v - wsum[lane];
            if (lane == NTH / 32 - 1) g_cnt[k] = v;
        }
        __syncthreads();

        int pos = woff[wid] + (inc - c);
        const int ob = k * MAXN;
#pragma unroll
        for (int i = 0; i < 16; i++) {
            if (vals[i] > 0.0f) {
                unsigned int q = (unsigned int)(vals[i] * QS20 + 0.5f);
                if (pos < MAXN)
                    g_list[ob + pos] = ((unsigned int)(base + i) << 20) | q;
                pos++;
            }
        }
    } else {
        // ---- blocked pixel-major lists: 64 pixels/CTA, 4 threads/pixel ----
        __shared__ int cq[4][64];

        const int pl = tid & 63;                       // local pixel
        const int qh = tid >> 6;                       // k-quarter: 0..3
        const int p  = (blockIdx.x - KK) * 64 + pl;    // global pixel
        const int kb = qh * 16;                        // k base for this quarter

        // blocked position of pixel p: block o, sub-slot within the 2x2
        const int py  = p >> 6, px = p & 63;
        const int o   = (py >> 1) * 32 + (px >> 1);
        const int sub = (py & 1) * 2 + (px & 1);
        const int col = o * 4 + sub;                   // column in g_p4 rows

        float vals[16];
#pragma unroll
        for (int i = 0; i < 16; i++)                   // 16 independent loads
            vals[i] = rfs[(kb + i) * HW + p];

        int c = 0;
#pragma unroll
        for (int i = 0; i < 16; i++) c += (vals[i] > 0.0f);

        cq[qh][pl] = c;
        __syncthreads();

        int n = 0;
#pragma unroll
        for (int h = 0; h < 4; h++) n += (h < qh) ? cq[h][pl] : 0;  // start
#pragma unroll
        for (int i = 0; i < 16; i++) {
            if (vals[i] > 0.0f) {
                g_p4[n * HW + col] = ((unsigned int)(kb + i) << 26) |
                                     (unsigned int)(vals[i] * QS26 + 0.5f);
                n++;
            }
        }
        if (qh == 3) g_n4[col] = n;                    // total count
    }
}

// ---------------------------------------------------------------------------
// Denominators: grid = NBC*8 = 1024 CTAs. CTA = (bc, octet of 8 k's); u tile
// in smem; each warp owns ONE k, unroll 8 => 8 list loads in flight.
// Numerics: e/denom == exp(v-m)/(exp(-m)+Sum exp(v-m)) exactly; |v| small.
// ---------------------------------------------------------------------------
__global__ __launch_bounds__(NTH) void denom_kernel(const float* __restrict__ u) {
    __shared__ float u_s[HW];

    const int bc   = blockIdx.x >> 3;
    const int oct  = blockIdx.x & 7;
    const int tid  = threadIdx.x;
    const int lane = tid & 31;
    const int wid  = tid >> 5;

    const float4* __restrict__ ub4 = reinterpret_cast<const float4*>(u + bc * HW);
#pragma unroll
    for (int i = 0; i < HW / 4 / NTH; i++)
        reinterpret_cast<float4*>(u_s)[tid + i * NTH] = ub4[tid + i * NTH];
    __syncthreads();

    const int k   = oct * 8 + wid;
    const int cnt = g_cnt[k];
    const unsigned int* __restrict__ ls = g_list + k * MAXN;

    float s = 0.0f;
    const int trips = (cnt + 31) >> 5;
#pragma unroll 8
    for (int j = 0; j < trips; j++) {
        const int t = lane + j * 32;
        const unsigned int e = ls[t];  // in-bounds (capacity MAXN); idx <= 4095
        const float ev = __expf(u_s[e >> 20] * ((float)(e & 0xFFFFFu) * INV_Q20));
        s += (t < cnt) ? ev : 0.0f;
    }
#pragma unroll
    for (int o = 16; o; o >>= 1) s += __shfl_xor_sync(0xffffffffu, s, o);
    if (lane == 0) g_inv[bc * KK + k] = __fdividef(1.0f, 1.0f + s);
}

// ---------------------------------------------------------------------------
// Gather + pool: grid = NBC*8 = 1024 CTAs, 128 threads. Each thread owns one
// 2x2 output block: per j-slot ONE coalesced uint4 load supplies all 4 pixel
// entries => 4 independent exp chains, unroll 4 => 16-deep MLP.
// Fixed per-pixel order => deterministic.
// ---------------------------------------------------------------------------
__global__ __launch_bounds__(128) void gather_kernel(const float* __restrict__ u,
                                                     float* __restrict__ out) {
    __shared__ float inv_s[KK];

    const int bc  = blockIdx.x >> 3;
    const int rg  = blockIdx.x & 7;
    const int tid = threadIdx.x;

    if (tid < KK) inv_s[tid] = g_inv[bc * KK + tid];
    __syncthreads();

    const int o   = rg * 128 + tid;       // block index in [0,1024)
    const int oy  = o >> 5;
    const int ox  = o & 31;
    const int p00 = oy * 128 + ox * 2;    // top-left pixel of the 2x2 block

    const float* __restrict__ ub = u + bc * HW;
    const float2 ua = *reinterpret_cast<const float2*>(ub + p00);
    const float2 uc = *reinterpret_cast<const float2*>(ub + p00 + 64);
    const float up[4] = {ua.x, ua.y, uc.x, uc.y};

    const int4 nn = *reinterpret_cast<const int4*>(g_n4 + o * 4);
    const int n[4] = {nn.x, nn.y, nn.z, nn.w};
    int mx = n[0];
#pragma unroll
    for (int i = 1; i < 4; i++) mx = (n[i] > mx) ? n[i] : mx;

    float acc[4] = {0.f, 0.f, 0.f, 0.f};
#pragma unroll 4
    for (int j = 0; j < mx; j++) {
        const uint4 e4 = *reinterpret_cast<const uint4*>(g_p4 + j * HW + o * 4);
        const unsigned int ent[4] = {e4.x, e4.y, e4.z, e4.w};
#pragma unroll
        for (int i = 0; i < 4; i++) {
            const float rf = (float)(ent[i] & 0x3FFFFFFu) * INV_Q26;
            const float e  = __expf(up[i] * rf) * inv_s[ent[i] >> 26];
            acc[i] += (j < n[i]) ? e : 0.0f;
        }
    }

    out[bc * 1024 + o] = fmaxf(fmaxf(acc[0], acc[1]), fmaxf(acc[2], acc[3]));
}

extern "C" void kernel_launch(void* const* d_in, const int* in_sizes, int n_in,
                              void* d_out, int out_size) {
    const float* u   = (const float*)d_in[0];  // (B,C,H,W) = 524288 f32
    const float* rfs = (const float*)d_in[1];  // (K,H,W)   = 262144 f32
    float* out = (float*)d_out;                // (B,C,32,32) = 131072 f32

    build_all<<<KK + HW / 64, NTH>>>(rfs);     // 128 CTAs
    denom_kernel<<<NBC * 8, NTH>>>(u);         // 1024 CTAs
    gather_kernel<<<NBC * 8, 128>>>(u, out);   // 1024 CTAs
}